// round 5
// baseline (speedup 1.0000x reference)
#include <cuda_runtime.h>
#include <math.h>

#define NB   8
#define NT   128
#define NS   400
#define NH   256
#define NVOC 50257
#define NBT  (NB * NT)

// ---------------- scratch (__device__ globals; no allocation allowed) --------
__device__ int    g_head[NB * NS];     // first-occurrence index of token at slot s
__device__ int    g_nheads[NB];        // distinct-token count per batch
__device__ float2 g_coeff[NBT];        // per (b,t): {p_gen, -(1-p)*lse}
__device__ float  g_corr[NBT * NS];    // per (b,t,head s): (1-p)*c_v  (heads only)

// ---------------- kernel 1: per-batch token dedup ----------------------------
__global__ void dedup_kernel(const int* __restrict__ tokens) {
    __shared__ int tok_sm[NS];
    __shared__ int cnt;
    const int b = blockIdx.x;
    const int s = threadIdx.x;
    if (s == 0) cnt = 0;
    if (s < NS) tok_sm[s] = tokens[b * NS + s];
    __syncthreads();
    if (s < NS) {
        const int mytok = tok_sm[s];
        int h = s;
        for (int j = 0; j < s; ++j) {
            if (tok_sm[j] == mytok) { h = j; break; }
        }
        g_head[b * NS + s] = h;
        if (h == s) atomicAdd(&cnt, 1);
    }
    __syncthreads();
    if (s == 0) g_nheads[b] = cnt;
}

// ---------------- kernel 2: fused p_gen + grouped-sum + lse per (b,t) --------
__global__ __launch_bounds__(256)
void rowstats_kernel(const float* __restrict__ ctx,
                     const float* __restrict__ din,
                     const float* __restrict__ dout,
                     const float* __restrict__ attn,
                     const float* __restrict__ Wc, const float* __restrict__ bc,
                     const float* __restrict__ Wo, const float* __restrict__ bo,
                     const float* __restrict__ Wi, const float* __restrict__ bi) {
    const int bt  = blockIdx.x;
    const int b   = bt / NT;
    const int tid = threadIdx.x;

    __shared__ float red[256];
    __shared__ float c_sm[NS];
    __shared__ float p_sh, m_sh;

    // --- p_gen: three H=256 dot products fused (one element per thread) ---
    const int base = bt * NH + tid;
    float partial = ctx[base]  * Wc[tid]
                  + dout[base] * Wo[tid]
                  + din[base]  * Wi[tid];

    // zero grouped-sum buffer
    c_sm[tid] = 0.0f;
    if (tid < NS - 256) c_sm[tid + 256] = 0.0f;

    red[tid] = partial;
    __syncthreads();
    for (int off = 128; off > 0; off >>= 1) {
        if (tid < off) red[tid] += red[tid + off];
        __syncthreads();
    }
    if (tid == 0) {
        const float z = red[0] + bc[0] + bo[0] + bi[0];
        p_sh = 1.0f / (1.0f + expf(-z));
    }
    __syncthreads();
    const float p = p_sh;

    // --- group attn values by canonical head (duplicates are rare) ---
    const int h0 = g_head[b * NS + tid];
    atomicAdd(&c_sm[h0], attn[bt * NS + tid]);
    int h1 = -1;
    if (tid < NS - 256) {
        h1 = g_head[b * NS + tid + 256];
        atomicAdd(&c_sm[h1], attn[bt * NS + tid + 256]);
    }
    __syncthreads();

    const bool head0 = (h0 == tid);
    const bool head1 = (h1 == tid + 256);
    const float c0 = head0 ? c_sm[tid]       : 0.0f;
    const float c1 = head1 ? c_sm[tid + 256] : 0.0f;

    // --- max over row (implicit zeros make 0 a valid floor; c >= 0 anyway) ---
    float m = 0.0f;
    if (head0) m = fmaxf(m, c0);
    if (head1) m = fmaxf(m, c1);
    red[tid] = m;
    __syncthreads();
    for (int off = 128; off > 0; off >>= 1) {
        if (tid < off) red[tid] = fmaxf(red[tid], red[tid + off]);
        __syncthreads();
    }
    if (tid == 0) m_sh = red[0];
    __syncthreads();
    m = m_sh;

    // --- sumexp over heads + (V - n) zeros ---
    float se = 0.0f;
    if (head0) se += expf(c0 - m);
    if (head1) se += expf(c1 - m);
    red[tid] = se;
    __syncthreads();
    for (int off = 128; off > 0; off >>= 1) {
        if (tid < off) red[tid] += red[tid + off];
        __syncthreads();
    }
    if (tid == 0) {
        const int n = g_nheads[b];
        const float total = red[0] + (float)(NVOC - n) * expf(-m);
        const float lse = m + logf(total);
        g_coeff[bt] = make_float2(p, -(1.0f - p) * lse);
    }

    // --- correction values for scatter pass ---
    if (head0) g_corr[bt * NS + tid]       = (1.0f - p) * c0;
    if (head1) g_corr[bt * NS + tid + 256] = (1.0f - p) * c1;
}

// ---------------- kernel 3: streaming affine mix (the bandwidth kernel) ------
// total elements = NBT*NVOC = 51,463,168 = 50257 * 1024 -> exactly
// 12,865,792 float4s = 50257 blocks * 256 threads. No bounds checks.
__global__ __launch_bounds__(256)
void mix_kernel(const float4* __restrict__ vocab, float4* __restrict__ out) {
    const unsigned i4   = blockIdx.x * 256u + threadIdx.x;
    const unsigned base = i4 * 4u;
    const float4 v = vocab[i4];

    const unsigned bt0 = base / (unsigned)NVOC;
    const unsigned rem = base - bt0 * (unsigned)NVOC;

    float4 o;
    if (rem <= (unsigned)(NVOC - 4)) {
        // entire float4 inside one row (the overwhelmingly common case)
        const float2 cf = g_coeff[bt0];
        o.x = fmaf(v.x, cf.x, cf.y);
        o.y = fmaf(v.y, cf.x, cf.y);
        o.z = fmaf(v.z, cf.x, cf.y);
        o.w = fmaf(v.w, cf.x, cf.y);
    } else {
        // straddles a row boundary (V odd): pick coeff per element
        const float2 cA = g_coeff[bt0];
        const float2 cB = g_coeff[bt0 + 1];
        const float2 e0 = (rem + 0u < (unsigned)NVOC) ? cA : cB;
        const float2 e1 = (rem + 1u < (unsigned)NVOC) ? cA : cB;
        const float2 e2 = (rem + 2u < (unsigned)NVOC) ? cA : cB;
        const float2 e3 = (rem + 3u < (unsigned)NVOC) ? cA : cB;
        o.x = fmaf(v.x, e0.x, e0.y);
        o.y = fmaf(v.y, e1.x, e1.y);
        o.z = fmaf(v.z, e2.x, e2.y);
        o.w = fmaf(v.w, e3.x, e3.y);
    }
    out[i4] = o;
}

// ---------------- kernel 4: sparse corrections at touched vocab ids ----------
__global__ __launch_bounds__(256)
void scatter_kernel(const int* __restrict__ tokens, float* __restrict__ out) {
    const int idx = blockIdx.x * 256 + threadIdx.x;
    if (idx >= NBT * NS) return;
    const int bt = idx / NS;
    const int s  = idx - bt * NS;
    const int b  = bt / NT;
    if (g_head[b * NS + s] != s) return;           // only canonical heads write
    const int v = tokens[b * NS + s];
    // distinct tokens within a row -> distinct addresses -> plain RMW is safe
    out[(size_t)bt * NVOC + v] += g_corr[idx];
}

// ---------------- launch ------------------------------------------------------
extern "C" void kernel_launch(void* const* d_in, const int* in_sizes, int n_in,
                              void* d_out, int out_size) {
    const int*   tokens = (const int*)  d_in[0];   // [B, S]
    const float* ctx    = (const float*)d_in[1];   // [B, T, H]
    const float* din    = (const float*)d_in[2];   // [B, T, H]
    const float* dout   = (const float*)d_in[3];   // [B, T, H]
    const float* vocab  = (const float*)d_in[4];   // [B, T, V]
    const float* attn   = (const float*)d_in[5];   // [B, T, S]
    // d_in[6] = encoder_outputs (unused by reference)
    const float* Wc = (const float*)d_in[7];
    const float* bc = (const float*)d_in[8];
    const float* Wo = (const float*)d_in[9];
    const float* bo = (const float*)d_in[10];
    const float* Wi = (const float*)d_in[11];
    const float* bi = (const float*)d_in[12];
    float* out = (float*)d_out;

    dedup_kernel<<<NB, 512>>>(tokens);
    rowstats_kernel<<<NBT, 256>>>(ctx, din, dout, attn, Wc, bc, Wo, bo, Wi, bi);
    mix_kernel<<<NVOC, 256>>>((const float4*)vocab, (float4*)out);
    scatter_kernel<<<(NBT * NS + 255) / 256, 256>>>(tokens, out);
}

// round 9
// speedup vs baseline: 1.0181x; 1.0181x over previous
#include <cuda_runtime.h>
#include <math.h>

#define NB   8
#define NT   128
#define NS   400
#define NH   256
#define NVOC 50257
#define NBT  (NB * NT)
#define BMW  1572              // bitmap words per batch: ceil(50257/32)=1571, +1 pad

// ---------------- scratch (__device__ globals; no allocation allowed) --------
__device__ int      g_head[NB * NS];    // first-occurrence index of token at slot s
__device__ int      g_nheads[NB];       // distinct-token count per batch
__device__ float2   g_coeff[NBT];       // per (b,t): {p_gen, -(1-p)*lse}
__device__ float    g_corr[NBT * NS];   // per (b,t,head s): (1-p)*c_v  (heads only)
__device__ unsigned g_bm[NB * BMW];     // per-b bitmap of touched vocab ids
__device__ short    g_sidx[NB * NVOC];  // per-b map: vocab id -> head slot (valid only where bit set)

// ---------------- kernel 1: per-batch dedup + bitmap + slot map --------------
__global__ void dedup_kernel(const int* __restrict__ tokens) {
    __shared__ int tok_sm[NS];
    __shared__ int cnt;
    const int b = blockIdx.x;
    const int t = threadIdx.x;
    if (t == 0) cnt = 0;
    // zero this batch's bitmap (graph replays reuse it)
    for (int i = t; i < BMW; i += 512) g_bm[b * BMW + i] = 0u;
    if (t < NS) tok_sm[t] = tokens[b * NS + t];
    __syncthreads();
    if (t < NS) {
        const int mytok = tok_sm[t];
        int h = t;
        for (int j = 0; j < t; ++j) {
            if (tok_sm[j] == mytok) { h = j; break; }
        }
        g_head[b * NS + t] = h;
        if (h == t) {
            atomicAdd(&cnt, 1);
            atomicOr(&g_bm[b * BMW + (mytok >> 5)], 1u << (mytok & 31));
            g_sidx[b * NVOC + mytok] = (short)t;
        }
    }
    __syncthreads();
    if (t == 0) g_nheads[b] = cnt;
}

// ---------------- block reductions: warp shuffle + 8-partial broadcast -------
__device__ __forceinline__ float block_sum_256(float v, float* red) {
    #pragma unroll
    for (int o = 16; o; o >>= 1) v += __shfl_xor_sync(0xffffffffu, v, o);
    if ((threadIdx.x & 31) == 0) red[threadIdx.x >> 5] = v;
    __syncthreads();
    float tot = red[0] + red[1] + red[2] + red[3] + red[4] + red[5] + red[6] + red[7];
    __syncthreads();
    return tot;
}
__device__ __forceinline__ float block_max_256(float v, float* red) {
    #pragma unroll
    for (int o = 16; o; o >>= 1) v = fmaxf(v, __shfl_xor_sync(0xffffffffu, v, o));
    if ((threadIdx.x & 31) == 0) red[threadIdx.x >> 5] = v;
    __syncthreads();
    float m = fmaxf(fmaxf(fmaxf(red[0], red[1]), fmaxf(red[2], red[3])),
                    fmaxf(fmaxf(red[4], red[5]), fmaxf(red[6], red[7])));
    __syncthreads();
    return m;
}

// ---------------- kernel 2: fused p_gen + grouped-sum + lse per (b,t) --------
__global__ __launch_bounds__(256)
void rowstats_kernel(const float* __restrict__ ctx,
                     const float* __restrict__ din,
                     const float* __restrict__ dout,
                     const float* __restrict__ attn,
                     const float* __restrict__ Wc, const float* __restrict__ bc,
                     const float* __restrict__ Wo, const float* __restrict__ bo,
                     const float* __restrict__ Wi, const float* __restrict__ bi) {
    const int bt  = blockIdx.x;
    const int b   = bt / NT;
    const int tid = threadIdx.x;

    __shared__ float red[8];
    __shared__ float c_sm[NS];

    // --- p_gen: three H=256 dot products fused (one element per thread) ---
    const int base = bt * NH + tid;
    float partial = ctx[base]  * Wc[tid]
                  + dout[base] * Wo[tid]
                  + din[base]  * Wi[tid];

    // zero grouped-sum buffer (no sync needed before the atomics' sync below)
    c_sm[tid] = 0.0f;
    if (tid < NS - 256) c_sm[tid + 256] = 0.0f;
    __syncthreads();

    const float z = block_sum_256(partial, red) + bc[0] + bo[0] + bi[0];
    const float p = 1.0f / (1.0f + expf(-z));
    const float q = 1.0f - p;

    // --- group attn values by canonical head (duplicates are rare) ---
    const int h0 = g_head[b * NS + tid];
    atomicAdd(&c_sm[h0], attn[bt * NS + tid]);
    int h1 = -1;
    if (tid < NS - 256) {
        h1 = g_head[b * NS + tid + 256];
        atomicAdd(&c_sm[h1], attn[bt * NS + tid + 256]);
    }
    __syncthreads();

    const bool head0 = (h0 == tid);
    const bool head1 = (h1 == tid + 256);
    const float c0 = head0 ? c_sm[tid]       : 0.0f;
    const float c1 = head1 ? c_sm[tid + 256] : 0.0f;

    // --- max over row (implicit zeros make 0 a valid floor; c >= 0 anyway) ---
    float m = 0.0f;
    if (head0) m = fmaxf(m, c0);
    if (head1) m = fmaxf(m, c1);
    m = block_max_256(m, red);

    // --- sumexp over heads + (V - n) zeros ---
    float se = 0.0f;
    if (head0) se += expf(c0 - m);
    if (head1) se += expf(c1 - m);
    se = block_sum_256(se, red);

    if (tid == 0) {
        const int n = g_nheads[b];
        const float total = se + (float)(NVOC - n) * expf(-m);
        const float lse = m + logf(total);
        g_coeff[bt] = make_float2(p, -q * lse);
    }

    // --- correction values for fused-mix lookup ---
    if (head0) g_corr[bt * NS + tid]       = q * c0;
    if (head1) g_corr[bt * NS + tid + 256] = q * c1;
}

// ---------------- kernel 3: streaming affine mix + fused sparse correction ---
// total elements = NBT*NVOC = 51,463,168 = 50257 * 1024 -> exactly
// 12,865,792 float4s = 50257 blocks * 256 threads. No bounds checks.
__global__ __launch_bounds__(256)
void mix_kernel(const float4* __restrict__ vocab, float4* __restrict__ out) {
    const unsigned i4   = blockIdx.x * 256u + threadIdx.x;
    const unsigned base = i4 * 4u;
    const float4 v = vocab[i4];

    const unsigned bt0 = base / (unsigned)NVOC;
    const unsigned rem = base - bt0 * (unsigned)NVOC;

    float4 o;
    if (rem <= (unsigned)(NVOC - 4)) {
        // entire float4 inside one row (the overwhelmingly common case)
        const float2 cf = g_coeff[bt0];
        o.x = fmaf(v.x, cf.x, cf.y);
        o.y = fmaf(v.y, cf.x, cf.y);
        o.z = fmaf(v.z, cf.x, cf.y);
        o.w = fmaf(v.w, cf.x, cf.y);

        // fused copy-dist correction: bitmap gate (L2-hot, 50 KB total)
        const unsigned b = bt0 >> 7;                 // bt / NT
        const unsigned* __restrict__ bm = g_bm + b * BMW;
        const unsigned w0 = rem >> 5;
        const unsigned sh = rem & 31u;
        unsigned bits = bm[w0] >> sh;
        if (sh > 28u) bits |= bm[w0 + 1] << (32u - sh);
        bits &= 15u;
        if (bits) {
            const short* __restrict__ sx   = g_sidx + b * NVOC;
            const float* __restrict__ corr = g_corr + bt0 * NS;
            if (bits & 1u) o.x += corr[sx[rem + 0u]];
            if (bits & 2u) o.y += corr[sx[rem + 1u]];
            if (bits & 4u) o.z += corr[sx[rem + 2u]];
            if (bits & 8u) o.w += corr[sx[rem + 3u]];
        }
    } else {
        // straddles a row boundary (V odd): fully general per-element path (rare)
        float vv[4] = {v.x, v.y, v.z, v.w};
        float oo[4];
        #pragma unroll
        for (int i = 0; i < 4; ++i) {
            const unsigned g  = base + (unsigned)i;
            const unsigned bt = g / (unsigned)NVOC;
            const unsigned r  = g - bt * (unsigned)NVOC;
            const unsigned b  = bt >> 7;
            const float2 cf = g_coeff[bt];
            float val = fmaf(vv[i], cf.x, cf.y);
            if ((g_bm[b * BMW + (r >> 5)] >> (r & 31u)) & 1u)
                val += g_corr[bt * NS + g_sidx[b * NVOC + r]];
            oo[i] = val;
        }
        o.x = oo[0]; o.y = oo[1]; o.z = oo[2]; o.w = oo[3];
    }
    out[i4] = o;
}

// ---------------- launch ------------------------------------------------------
extern "C" void kernel_launch(void* const* d_in, const int* in_sizes, int n_in,
                              void* d_out, int out_size) {
    const int*   tokens = (const int*)  d_in[0];   // [B, S]
    const float* ctx    = (const float*)d_in[1];   // [B, T, H]
    const float* din    = (const float*)d_in[2];   // [B, T, H]
    const float* dout   = (const float*)d_in[3];   // [B, T, H]
    const float* vocab  = (const float*)d_in[4];   // [B, T, V]
    const float* attn   = (const float*)d_in[5];   // [B, T, S]
    // d_in[6] = encoder_outputs (unused by reference)
    const float* Wc = (const float*)d_in[7];
    const float* bc = (const float*)d_in[8];
    const float* Wo = (const float*)d_in[9];
    const float* bo = (const float*)d_in[10];
    const float* Wi = (const float*)d_in[11];
    const float* bi = (const float*)d_in[12];
    float* out = (float*)d_out;

    dedup_kernel<<<NB, 512>>>(tokens);
    rowstats_kernel<<<NBT, 256>>>(ctx, din, dout, attn, Wc, bc, Wo, bo, Wi, bi);
    mix_kernel<<<NVOC, 256>>>((const float4*)vocab, (float4*)out);
}

// round 10
// speedup vs baseline: 1.2951x; 1.2721x over previous
#include <cuda_runtime.h>
#include <math.h>

#define NB   8
#define NT   128
#define NS   400
#define NH   256
#define NVOC 50257
#define NBT  (NB * NT)
#define BMW  1572              // bitmap words per batch: ceil(50257/32)=1571, +1 pad
#define HSZ  1024              // dedup hash table slots (power of two)

// ---------------- scratch (__device__ globals; no allocation allowed) --------
__device__ int      g_head[NB * NS];    // canonical occurrence index of token at slot s
__device__ int      g_nheads[NB];       // distinct-token count per batch
__device__ float2   g_coeff[NBT];       // per (b,t): {p_gen, -(1-p)*lse}
__device__ float    g_corr[NBT * NS];   // per (b,t,head s): (1-p)*c_v  (heads only)
__device__ unsigned g_bm[NB * BMW];     // per-b bitmap of touched vocab ids
__device__ short    g_sidx[NB * NVOC];  // per-b map: vocab id -> head slot (valid only where bit set)

// ---------------- kernel 1: per-batch dedup via shared-mem hash table --------
// 400 tokens -> 1024-slot open-addressing table. atomicCAS claims a key slot;
// atomicMin elects the lowest occurrence index as the canonical head. Any
// consistent representative is correct (grouped sums gather ALL duplicates).
__global__ __launch_bounds__(512)
void dedup_kernel(const int* __restrict__ tokens) {
    __shared__ int hkey[HSZ];
    __shared__ int hrep[HSZ];
    __shared__ int cnt;
    const int b = blockIdx.x;
    const int t = threadIdx.x;

    hkey[t] = -1;  hkey[t + 512] = -1;
    hrep[t] = 0x7fffffff;  hrep[t + 512] = 0x7fffffff;
    if (t == 0) cnt = 0;
    // zero this batch's bitmap (graph replays reuse it)
    #pragma unroll
    for (int i = t; i < BMW; i += 512) g_bm[b * BMW + i] = 0u;
    __syncthreads();

    int tok = -1;
    unsigned slot = 0;
    if (t < NS) {
        tok = tokens[b * NS + t];
        unsigned h = ((unsigned)tok * 2654435761u) & (HSZ - 1u);
        // probe entirely through atomicCAS (avoids stale plain-LDS reads)
        for (;;) {
            const int old = atomicCAS(&hkey[h], -1, tok);
            if (old == -1 || old == tok) break;
            h = (h + 1u) & (HSZ - 1u);
        }
        slot = h;
        atomicMin(&hrep[h], t);
    }
    __syncthreads();

    if (t < NS) {
        const int head = hrep[slot];
        g_head[b * NS + t] = head;
        if (head == t) {
            atomicAdd(&cnt, 1);
            atomicOr(&g_bm[b * BMW + ((unsigned)tok >> 5)], 1u << (tok & 31));
            g_sidx[b * NVOC + tok] = (short)t;
        }
    }
    __syncthreads();
    if (t == 0) g_nheads[b] = cnt;
}

// ---------------- block reductions: warp shuffle + 8-partial broadcast -------
__device__ __forceinline__ float block_sum_256(float v, float* red) {
    #pragma unroll
    for (int o = 16; o; o >>= 1) v += __shfl_xor_sync(0xffffffffu, v, o);
    if ((threadIdx.x & 31) == 0) red[threadIdx.x >> 5] = v;
    __syncthreads();
    float tot = red[0] + red[1] + red[2] + red[3] + red[4] + red[5] + red[6] + red[7];
    __syncthreads();
    return tot;
}
__device__ __forceinline__ float block_max_256(float v, float* red) {
    #pragma unroll
    for (int o = 16; o; o >>= 1) v = fmaxf(v, __shfl_xor_sync(0xffffffffu, v, o));
    if ((threadIdx.x & 31) == 0) red[threadIdx.x >> 5] = v;
    __syncthreads();
    float m = fmaxf(fmaxf(fmaxf(red[0], red[1]), fmaxf(red[2], red[3])),
                    fmaxf(fmaxf(red[4], red[5]), fmaxf(red[6], red[7])));
    __syncthreads();
    return m;
}

// ---------------- kernel 2: fused p_gen + grouped-sum + lse per (b,t) --------
__global__ __launch_bounds__(256)
void rowstats_kernel(const float* __restrict__ ctx,
                     const float* __restrict__ din,
                     const float* __restrict__ dout,
                     const float* __restrict__ attn,
                     const float* __restrict__ Wc, const float* __restrict__ bc,
                     const float* __restrict__ Wo, const float* __restrict__ bo,
                     const float* __restrict__ Wi, const float* __restrict__ bi) {
    const int bt  = blockIdx.x;
    const int b   = bt / NT;
    const int tid = threadIdx.x;

    __shared__ float red[8];
    __shared__ float c_sm[NS];

    // --- p_gen: three H=256 dot products fused (one element per thread) ---
    const int base = bt * NH + tid;
    float partial = ctx[base]  * Wc[tid]
                  + dout[base] * Wo[tid]
                  + din[base]  * Wi[tid];

    c_sm[tid] = 0.0f;
    if (tid < NS - 256) c_sm[tid + 256] = 0.0f;
    __syncthreads();

    const float z = block_sum_256(partial, red) + bc[0] + bo[0] + bi[0];
    const float p = 1.0f / (1.0f + expf(-z));
    const float q = 1.0f - p;

    // --- group attn values by canonical head (duplicates are rare) ---
    const int h0 = g_head[b * NS + tid];
    atomicAdd(&c_sm[h0], attn[bt * NS + tid]);
    int h1 = -1;
    if (tid < NS - 256) {
        h1 = g_head[b * NS + tid + 256];
        atomicAdd(&c_sm[h1], attn[bt * NS + tid + 256]);
    }
    __syncthreads();

    const bool head0 = (h0 == tid);
    const bool head1 = (h1 == tid + 256);
    const float c0 = head0 ? c_sm[tid]       : 0.0f;
    const float c1 = head1 ? c_sm[tid + 256] : 0.0f;

    // --- max over row (implicit zeros make 0 a valid floor; c >= 0 anyway) ---
    float m = 0.0f;
    if (head0) m = fmaxf(m, c0);
    if (head1) m = fmaxf(m, c1);
    m = block_max_256(m, red);

    // --- sumexp over heads + (V - n) zeros ---
    float se = 0.0f;
    if (head0) se += expf(c0 - m);
    if (head1) se += expf(c1 - m);
    se = block_sum_256(se, red);

    if (tid == 0) {
        const int n = g_nheads[b];
        const float total = se + (float)(NVOC - n) * expf(-m);
        const float lse = m + logf(total);
        g_coeff[bt] = make_float2(p, -q * lse);
    }

    // --- correction values for fused-mix lookup ---
    if (head0) g_corr[bt * NS + tid]       = q * c0;
    if (head1) g_corr[bt * NS + tid + 256] = q * c1;
}

// ---------------- kernel 3: streaming affine mix + fused sparse correction ---
// total elements = NBT*NVOC = 51,463,168 = 50257 * 1024 -> exactly
// 12,865,792 float4s = 50257 blocks * 256 threads. No bounds checks.
__global__ __launch_bounds__(256)
void mix_kernel(const float4* __restrict__ vocab, float4* __restrict__ out) {
    const unsigned i4   = blockIdx.x * 256u + threadIdx.x;
    const unsigned base = i4 * 4u;
    const float4 v = __ldcs(&vocab[i4]);      // streaming read: don't pollute L2

    const unsigned bt0 = base / (unsigned)NVOC;
    const unsigned rem = base - bt0 * (unsigned)NVOC;

    float4 o;
    if (rem <= (unsigned)(NVOC - 4)) {
        // entire float4 inside one row (the overwhelmingly common case)
        const float2 cf = g_coeff[bt0];
        o.x = fmaf(v.x, cf.x, cf.y);
        o.y = fmaf(v.y, cf.x, cf.y);
        o.z = fmaf(v.z, cf.x, cf.y);
        o.w = fmaf(v.w, cf.x, cf.y);

        // fused copy-dist correction: bitmap gate (L2-hot, 50 KB total)
        const unsigned b = bt0 >> 7;                 // bt / NT
        const unsigned* __restrict__ bm = g_bm + b * BMW;
        const unsigned w0 = rem >> 5;
        const unsigned sh = rem & 31u;
        unsigned bits = bm[w0] >> sh;
        if (sh > 28u) bits |= bm[w0 + 1] << (32u - sh);
        bits &= 15u;
        if (bits) {
            const short* __restrict__ sx   = g_sidx + b * NVOC;
            const float* __restrict__ corr = g_corr + bt0 * NS;
            if (bits & 1u) o.x += corr[sx[rem + 0u]];
            if (bits & 2u) o.y += corr[sx[rem + 1u]];
            if (bits & 4u) o.z += corr[sx[rem + 2u]];
            if (bits & 8u) o.w += corr[sx[rem + 3u]];
        }
    } else {
        // straddles a row boundary (V odd): fully general per-element path (rare)
        float vv[4] = {v.x, v.y, v.z, v.w};
        float oo[4];
        #pragma unroll
        for (int i = 0; i < 4; ++i) {
            const unsigned g  = base + (unsigned)i;
            const unsigned bt = g / (unsigned)NVOC;
            const unsigned r  = g - bt * (unsigned)NVOC;
            const unsigned b  = bt >> 7;
            const float2 cf = g_coeff[bt];
            float val = fmaf(vv[i], cf.x, cf.y);
            if ((g_bm[b * BMW + (r >> 5)] >> (r & 31u)) & 1u)
                val += g_corr[bt * NS + g_sidx[b * NVOC + r]];
            oo[i] = val;
        }
        o.x = oo[0]; o.y = oo[1]; o.z = oo[2]; o.w = oo[3];
    }
    __stcs(&out[i4], o);                      // streaming write
}

// ---------------- launch ------------------------------------------------------
extern "C" void kernel_launch(void* const* d_in, const int* in_sizes, int n_in,
                              void* d_out, int out_size) {
    const int*   tokens = (const int*)  d_in[0];   // [B, S]
    const float* ctx    = (const float*)d_in[1];   // [B, T, H]
    const float* din    = (const float*)d_in[2];   // [B, T, H]
    const float* dout   = (const float*)d_in[3];   // [B, T, H]
    const float* vocab  = (const float*)d_in[4];   // [B, T, V]
    const float* attn   = (const float*)d_in[5];   // [B, T, S]
    // d_in[6] = encoder_outputs (unused by reference)
    const float* Wc = (const float*)d_in[7];
    const float* bc = (const float*)d_in[8];
    const float* Wo = (const float*)d_in[9];
    const float* bo = (const float*)d_in[10];
    const float* Wi = (const float*)d_in[11];
    const float* bi = (const float*)d_in[12];
    float* out = (float*)d_out;

    dedup_kernel<<<NB, 512>>>(tokens);
    rowstats_kernel<<<NBT, 256>>>(ctx, din, dout, attn, Wc, bc, Wo, bo, Wi, bi);
    mix_kernel<<<NVOC, 256>>>((const float4*)vocab, (float4*)out);
}